// round 11
// baseline (speedup 1.0000x reference)
#include <cuda_runtime.h>
#include <cuda_bf16.h>
#include <math.h>
#include <stdint.h>

#define B_SZ    2
#define L_SEQ   2048
#define D_MODEL 768
#define D_INNER 1536
#define E2      3072
#define D_STATE 16
#define DT_RANK 48
#define KDBL    80
#define D_CONV  4
#define NCH     16
#define CL      (L_SEQ / NCH)          // 128
#define R_TOT   (2 * B_SZ * D_INNER)   // 6144

// ---------------- scratch (device globals) ----------------
__device__ float g_xz  [B_SZ * E2 * L_SEQ];
__device__ float g_xc  [2][B_SZ * D_INNER * L_SEQ];
__device__ float g_xdp [2 * B_SZ * 128 * L_SEQ];        // padded x_dbl: [br][b][128][L]
__device__ float g_dt  [2][B_SZ * D_INNER * L_SEQ];
__device__ float g_bc  [2][B_SZ * L_SEQ * 32];
__device__ float g_y   [2][B_SZ * D_INNER * L_SEQ];
// chunked-scan intermediates: [r][c][n]
__device__ float g_P  [R_TOT * NCH * D_STATE];
__device__ float g_q  [R_TOT * NCH * D_STATE];
__device__ float g_hin[R_TOT * NCH * D_STATE];

// bf16 hi/lo split buffers
__device__ __nv_bfloat16 g_winh[E2 * D_MODEL],      g_winl[E2 * D_MODEL];
__device__ __nv_bfloat16 g_hidh[B_SZ * L_SEQ * D_MODEL], g_hidl[B_SZ * L_SEQ * D_MODEL];
__device__ __nv_bfloat16 g_wouth[D_MODEL * D_INNER], g_woutl[D_MODEL * D_INNER];
__device__ __nv_bfloat16 g_chi[B_SZ * L_SEQ * D_INNER], g_clo[B_SZ * L_SEQ * D_INNER];
__device__ __nv_bfloat16 g_xth[2 * B_SZ * L_SEQ * D_INNER], g_xtl[2 * B_SZ * L_SEQ * D_INNER];
__device__ __nv_bfloat16 g_wxph[2 * 128 * D_INNER], g_wxpl[2 * 128 * D_INNER];

// ================= helpers =================
__device__ __forceinline__ uint32_t smem_u32(const void* p) {
    uint32_t a;
    asm("{ .reg .u64 t; cvta.to.shared.u64 t, %1; cvt.u32.u64 %0, t; }" : "=r"(a) : "l"(p));
    return a;
}
__device__ __forceinline__ void cp16(uint32_t s, const void* g) {
    asm volatile("cp.async.cg.shared.global [%0], [%1], 16;" :: "r"(s), "l"(g));
}
#define CP_COMMIT() asm volatile("cp.async.commit_group;" ::: "memory")
#define CP_WAIT(N)  asm volatile("cp.async.wait_group %0;" :: "n"(N) : "memory")

#define LDMX4(r, addr) \
    asm volatile("ldmatrix.sync.aligned.m8n8.x4.shared.b16 {%0,%1,%2,%3}, [%4];" \
        : "=r"((r)[0]), "=r"((r)[1]), "=r"((r)[2]), "=r"((r)[3]) : "r"(addr))
#define LDMX2(r, addr) \
    asm volatile("ldmatrix.sync.aligned.m8n8.x2.shared.b16 {%0,%1}, [%2];" \
        : "=r"((r)[0]), "=r"((r)[1]) : "r"(addr))
#define MMA(c, a, b) \
    asm volatile("mma.sync.aligned.m16n8k16.row.col.f32.bf16.bf16.f32 " \
        "{%0,%1,%2,%3}, {%4,%5,%6,%7}, {%8,%9}, {%0,%1,%2,%3};" \
        : "+f"((c)[0]), "+f"((c)[1]), "+f"((c)[2]), "+f"((c)[3]) \
        : "r"((a)[0]), "r"((a)[1]), "r"((a)[2]), "r"((a)[3]), "r"((b)[0]), "r"((b)[1]))

// ================= bf16x3 mma.sync GEMM, 4-stage pipeline =================
#define GM_PAD 40

template<int TN>
__global__ void __launch_bounds__(256, 1) gemm_mma(
    const __nv_bfloat16* __restrict__ Ahi, const __nv_bfloat16* __restrict__ Alo,
    const __nv_bfloat16* __restrict__ Bhi, const __nv_bfloat16* __restrict__ Blo,
    float* __restrict__ C, int K, int ldc,
    long sAb, long sAr, long sBb, long sBr, long sCb, long sCr)
{
    constexpr int TM = 128;
    constexpr int AT = TM * GM_PAD * 2;
    constexpr int BT = TN * GM_PAD * 2;
    constexpr int STG = 2 * AT + 2 * BT;
    constexpr int WN = TN / 4;
    constexpr int NI = WN / 8;
    extern __shared__ char smem[];
    uint32_t sb = smem_u32(smem);
    int tid = threadIdx.x, lane = tid & 31, warp = tid >> 5;
    int wm = warp >> 2, wn = warp & 3;
    int m0 = blockIdx.y * TM, n0 = blockIdx.x * TN;
    long zb = blockIdx.z & 1, zr = blockIdx.z >> 1;

    const __nv_bfloat16* ah  = Ahi + zb * sAb + zr * sAr + (size_t)m0 * K;
    const __nv_bfloat16* al  = Alo + zb * sAb + zr * sAr + (size_t)m0 * K;
    const __nv_bfloat16* bh  = Bhi + zb * sBb + zr * sBr + (size_t)n0 * K;
    const __nv_bfloat16* bl_ = Blo + zb * sBb + zr * sBr + (size_t)n0 * K;
    C += zb * sCb + zr * sCr;

    int nk = K >> 5;

    auto stage = [&](int slot, int kt) {
        int k0 = kt << 5;
        uint32_t base = sb + slot * STG;
        #pragma unroll
        for (int j = tid; j < TM * 4; j += 256) {
            int r = j >> 2, c = (j & 3) * 8;
            uint32_t off = (uint32_t)(r * GM_PAD + c) * 2;
            cp16(base + off,      ah + (size_t)r * K + k0 + c);
            cp16(base + AT + off, al + (size_t)r * K + k0 + c);
        }
        #pragma unroll
        for (int j = tid; j < TN * 4; j += 256) {
            int r = j >> 2, c = (j & 3) * 8;
            uint32_t off = (uint32_t)(r * GM_PAD + c) * 2;
            cp16(base + 2 * AT + off,      bh  + (size_t)r * K + k0 + c);
            cp16(base + 2 * AT + BT + off, bl_ + (size_t)r * K + k0 + c);
        }
    };

    float acc[4][NI][4] = {};

    stage(0, 0); CP_COMMIT();
    stage(1, 1); CP_COMMIT();
    stage(2, 2); CP_COMMIT();

    int a_row  = wm * 64 + (lane & 15);
    int a_koff = 8 * (lane >> 4);
    int b_row  = wn * WN + (lane & 7);
    int b_koff = 8 * ((lane >> 3) & 1);

    for (int kt = 0; kt < nk; kt++) {
        int pend = nk - kt;
        if (pend >= 3)      CP_WAIT(2);
        else if (pend == 2) CP_WAIT(1);
        else                CP_WAIT(0);
        __syncthreads();

        uint32_t tb = sb + (kt & 3) * STG;
        #pragma unroll
        for (int ks = 0; ks < 2; ks++) {
            int kb = ks * 16;
            uint32_t afh[4][4], afl[4][4], bfh[NI][2], bfl[NI][2];
            #pragma unroll
            for (int mi = 0; mi < 4; mi++) {
                uint32_t ad = tb + (uint32_t)((a_row + mi * 16) * GM_PAD + kb + a_koff) * 2;
                LDMX4(afh[mi], ad);
                LDMX4(afl[mi], ad + AT);
            }
            #pragma unroll
            for (int ni = 0; ni < NI; ni++) {
                uint32_t bd = tb + 2 * AT + (uint32_t)((b_row + ni * 8) * GM_PAD + kb + b_koff) * 2;
                LDMX2(bfh[ni], bd);
                LDMX2(bfl[ni], bd + BT);
            }
            #pragma unroll
            for (int mi = 0; mi < 4; mi++)
                #pragma unroll
                for (int ni = 0; ni < NI; ni++) MMA(acc[mi][ni], afh[mi], bfh[ni]);
            #pragma unroll
            for (int mi = 0; mi < 4; mi++)
                #pragma unroll
                for (int ni = 0; ni < NI; ni++) MMA(acc[mi][ni], afh[mi], bfl[ni]);
            #pragma unroll
            for (int mi = 0; mi < 4; mi++)
                #pragma unroll
                for (int ni = 0; ni < NI; ni++) MMA(acc[mi][ni], afl[mi], bfh[ni]);
        }
        if (kt + 3 < nk) { stage((kt + 3) & 3, kt + 3); CP_COMMIT(); }
    }

    int gid = lane >> 2, tig = lane & 3;
    #pragma unroll
    for (int mi = 0; mi < 4; mi++) {
        int row = m0 + wm * 64 + mi * 16 + gid;
        #pragma unroll
        for (int ni = 0; ni < NI; ni++) {
            int col = n0 + wn * WN + ni * 8 + tig * 2;
            *(float2*)(C + (size_t)row * ldc + col)       = make_float2(acc[mi][ni][0], acc[mi][ni][1]);
            *(float2*)(C + (size_t)(row + 8) * ldc + col) = make_float2(acc[mi][ni][2], acc[mi][ni][3]);
        }
    }
}

// ================= merged prep: all fp32->bf16 hi/lo splits + padded W_x =================
__global__ void prep_kernel(const float* __restrict__ W_in, const float* __restrict__ hidden,
                            const float* __restrict__ W_out,
                            const float* __restrict__ Wx, const float* __restrict__ Wxb,
                            __nv_bfloat16* __restrict__ winh, __nv_bfloat16* __restrict__ winl,
                            __nv_bfloat16* __restrict__ hidh, __nv_bfloat16* __restrict__ hidl,
                            __nv_bfloat16* __restrict__ wouth, __nv_bfloat16* __restrict__ woutl,
                            __nv_bfloat16* __restrict__ wxph, __nv_bfloat16* __restrict__ wxpl)
{
    int i = blockIdx.x * 256 + threadIdx.x;
    int seg = blockIdx.y;
    const float* s; __nv_bfloat16 *hi, *lo; int n;
    if (seg == 0)      { s = W_in;  hi = winh;  lo = winl;  n = E2 * D_MODEL; }
    else if (seg == 1) { s = hidden; hi = hidh; lo = hidl;  n = B_SZ * L_SEQ * D_MODEL; }
    else if (seg == 2) { s = W_out; hi = wouth; lo = woutl; n = D_MODEL * D_INNER; }
    else {
        n = 2 * 128 * D_INNER;
        if (i >= n) return;
        int br = i / (128 * D_INNER);
        int j  = i % (128 * D_INNER);
        int r  = j / D_INNER;
        float v = (r < KDBL) ? (br ? Wxb : Wx)[j] : 0.f;
        __nv_bfloat16 hh = __float2bfloat16(v);
        wxph[i] = hh;
        wxpl[i] = __float2bfloat16(v - __bfloat162float(hh));
        return;
    }
    if (i >= n) return;
    float v = s[i];
    __nv_bfloat16 h = __float2bfloat16(v);
    hi[i] = h;
    lo[i] = __float2bfloat16(v - __bfloat162float(h));
}

// ================= conv + SiLU: fp32 [d][t] + bf16 hi/lo transposed [t][d] =================
__global__ void conv_silu_t(const float* __restrict__ xz,
                            const float* __restrict__ w0, const float* __restrict__ b0,
                            const float* __restrict__ w1, const float* __restrict__ b1,
                            float* __restrict__ xc0, float* __restrict__ xc1,
                            __nv_bfloat16* __restrict__ xth, __nv_bfloat16* __restrict__ xtl)
{
    __shared__ float s[32][33];
    int z = blockIdx.z, b = z & 1, rev = z >> 1;
    const float* w    = rev ? w1 : w0;
    const float* bias = rev ? b1 : b0;
    float* xc = (rev ? xc1 : xc0) + (size_t)b * D_INNER * L_SEQ;
    __nv_bfloat16* th = xth + ((size_t)(rev * B_SZ + b) * L_SEQ) * D_INNER;
    __nv_bfloat16* tl = xtl + ((size_t)(rev * B_SZ + b) * L_SEQ) * D_INNER;
    int t0 = blockIdx.x * 32, d0 = blockIdx.y * 32;
    int tid = threadIdx.x;
    int tt = tid & 31, dg = tid >> 5;

    #pragma unroll
    for (int i = 0; i < 4; i++) {
        int d = d0 + dg + i * 8;
        int t = t0 + tt;
        const float* xp = xz + ((size_t)b * E2 + d) * L_SEQ;
        float acc = bias[d];
        #pragma unroll
        for (int k = 0; k < 4; k++) {
            int ss = t - 3 + k;
            float xv = 0.f;
            if (ss >= 0) xv = xp[rev ? (L_SEQ - 1 - ss) : ss];
            acc = fmaf(w[d * 4 + k], xv, acc);
        }
        float v = acc / (1.f + __expf(-acc));
        xc[(size_t)d * L_SEQ + t] = v;
        s[dg + i * 8][tt] = v;
    }
    __syncthreads();
    #pragma unroll
    for (int i = 0; i < 4; i++) {
        int t = t0 + dg + i * 8;
        int d = d0 + tt;
        float v = s[tt][dg + i * 8];
        __nv_bfloat16 h = __float2bfloat16(v);
        size_t o = (size_t)t * D_INNER + d;
        th[o] = h;
        tl[o] = __float2bfloat16(v - __bfloat162float(h));
    }
}

// ================= dt =================
#define DT_DC 96
__global__ void __launch_bounds__(256) dt_kernel2(
    const float* __restrict__ xdp,
    const float* __restrict__ Wdt, const float* __restrict__ Wdtb,
    const float* __restrict__ bdt, const float* __restrict__ bdtb,
    float* __restrict__ dt0, float* __restrict__ dt1)
{
    __shared__ float sw_[DT_DC][DT_RANK];
    int z = blockIdx.z, b = z & 1, br = z >> 1;
    const float* xd = xdp + (size_t)(br * B_SZ + b) * 128 * L_SEQ;
    const float* W  = br ? Wdtb : Wdt;
    const float* bb = br ? bdtb : bdt;
    float* out = (br ? dt1 : dt0) + (size_t)b * D_INNER * L_SEQ;
    int tid = threadIdx.x;
    int t  = blockIdx.x * 256 + tid;
    int d0 = blockIdx.y * DT_DC;

    float xr[DT_RANK];
    #pragma unroll
    for (int r = 0; r < DT_RANK; r++) xr[r] = xd[(size_t)r * L_SEQ + t];
    for (int i = tid; i < DT_DC * DT_RANK; i += 256) sw_[i / DT_RANK][i % DT_RANK] = W[d0 * DT_RANK + i];
    __syncthreads();

    for (int dd = 0; dd < DT_DC; dd++) {
        float acc = __ldg(bb + d0 + dd);
        #pragma unroll
        for (int r = 0; r < DT_RANK; r++) acc = fmaf(sw_[dd][r], xr[r], acc);
        float sp = (acc > 20.f) ? acc : log1pf(__expf(acc));
        out[(size_t)(d0 + dd) * L_SEQ + t] = sp;
    }
}

// ================= B/C transpose =================
__global__ void bc_kernel(const float* __restrict__ xdp,
                          float* __restrict__ bc0, float* __restrict__ bc1)
{
    int idx = blockIdx.x * 256 + threadIdx.x;
    int br = idx >> 17;
    int j  = idx & 131071;
    int i  = j & 31, t = (j >> 5) & (L_SEQ - 1), b = j >> 16;
    float* bc = br ? bc1 : bc0;
    bc[j] = xdp[((size_t)(br * B_SZ + b) * 128 + DT_RANK + i) * L_SEQ + t];
}

// ================= chunked scan, pass 1: per-chunk (P = prod dA, q = local end state) =================
__global__ void scan_part1(const float* __restrict__ xc0, const float* __restrict__ xc1,
                           const float* __restrict__ dt0, const float* __restrict__ dt1,
                           const float* __restrict__ bc0, const float* __restrict__ bc1,
                           const float* __restrict__ Af, const float* __restrict__ Ab,
                           float* __restrict__ Pout, float* __restrict__ qout)
{
    int half = threadIdx.x >> 4;
    int n    = threadIdx.x & 15;
    int r    = blockIdx.x * 16 + half;        // global row 0..R_TOT
    int c    = blockIdx.y;                    // chunk
    int br   = r / (B_SZ * D_INNER);
    int rowin = r % (B_SZ * D_INNER);
    int b = rowin / D_INNER, d = rowin % D_INNER;

    const float* Alog = br ? Ab : Af;
    const float* dtp = (br ? dt1 : dt0) + (size_t)rowin * L_SEQ + c * CL;
    const float* xp  = (br ? xc1 : xc0) + (size_t)rowin * L_SEQ + c * CL;
    const float* bcp = (br ? bc1 : bc0) + (size_t)b * L_SEQ * 32 + (size_t)c * CL * 32;

    float a = -__expf(Alog[d * D_STATE + n]);
    float h = 0.f, P = 1.f;
    for (int t = 0; t < CL; t += 4) {
        float4 dt4 = *(const float4*)(dtp + t);
        float4 x4  = *(const float4*)(xp + t);
        float dts[4] = {dt4.x, dt4.y, dt4.z, dt4.w};
        float xs[4]  = {x4.x,  x4.y,  x4.z,  x4.w};
        float bvv[4];
        #pragma unroll
        for (int j = 0; j < 4; j++) bvv[j] = __ldg(bcp + (t + j) * 32 + n);
        #pragma unroll
        for (int j = 0; j < 4; j++) {
            float dA = __expf(dts[j] * a);
            P *= dA;
            h = fmaf(dA, h, dts[j] * xs[j] * bvv[j]);
        }
    }
    size_t o = ((size_t)r * NCH + c) * D_STATE + n;
    Pout[o] = P;
    qout[o] = h;
}

// ================= chunked scan, pass 2: serial prefix over chunks =================
__global__ void scan_prefix(const float* __restrict__ P, const float* __restrict__ q,
                            float* __restrict__ hin)
{
    int idx = blockIdx.x * 256 + threadIdx.x;      // over R_TOT*16
    int r = idx >> 4, n = idx & 15;
    float h = 0.f;
    #pragma unroll
    for (int c = 0; c < NCH; c++) {
        size_t o = ((size_t)r * NCH + c) * D_STATE + n;
        hin[o] = h;
        h = fmaf(P[o], h, q[o]);
    }
}

// ================= chunked scan, pass 3: y with correct initial states =================
__global__ void scan_part2(const float* __restrict__ xc0, const float* __restrict__ xc1,
                           const float* __restrict__ dt0, const float* __restrict__ dt1,
                           const float* __restrict__ bc0, const float* __restrict__ bc1,
                           const float* __restrict__ Af, const float* __restrict__ Ab,
                           const float* __restrict__ Df, const float* __restrict__ Db,
                           const float* __restrict__ hin,
                           float* __restrict__ y0, float* __restrict__ y1)
{
    int half = threadIdx.x >> 4;
    int n    = threadIdx.x & 15;
    int r    = blockIdx.x * 16 + half;
    int c    = blockIdx.y;
    int br   = r / (B_SZ * D_INNER);
    int rowin = r % (B_SZ * D_INNER);
    int b = rowin / D_INNER, d = rowin % D_INNER;

    const float* Alog = br ? Ab : Af;
    const float* Dp   = br ? Db : Df;
    const float* dtp = (br ? dt1 : dt0) + (size_t)rowin * L_SEQ + c * CL;
    const float* xp  = (br ? xc1 : xc0) + (size_t)rowin * L_SEQ + c * CL;
    const float* bcp = (br ? bc1 : bc0) + (size_t)b * L_SEQ * 32 + (size_t)c * CL * 32;
    float* yp = (br ? y1 : y0) + (size_t)rowin * L_SEQ + c * CL;

    float a  = -__expf(Alog[d * D_STATE + n]);
    float Dv = Dp[d];
    float h  = hin[((size_t)r * NCH + c) * D_STATE + n];

    for (int t = 0; t < CL; t += 4) {
        float4 dt4 = *(const float4*)(dtp + t);
        float4 x4  = *(const float4*)(xp + t);
        float dts[4] = {dt4.x, dt4.y, dt4.z, dt4.w};
        float xs[4]  = {x4.x,  x4.y,  x4.z,  x4.w};
        float bvv[4], cvv[4];
        #pragma unroll
        for (int j = 0; j < 4; j++) {
            bvv[j] = __ldg(bcp + (t + j) * 32 + n);
            cvv[j] = __ldg(bcp + (t + j) * 32 + 16 + n);
        }
        #pragma unroll
        for (int j = 0; j < 4; j++) {
            float dA = __expf(dts[j] * a);
            h = fmaf(dA, h, dts[j] * xs[j] * bvv[j]);
            float p = h * cvv[j];
            p += __shfl_xor_sync(0xffffffffu, p, 1);
            p += __shfl_xor_sync(0xffffffffu, p, 2);
            p += __shfl_xor_sync(0xffffffffu, p, 4);
            p += __shfl_xor_sync(0xffffffffu, p, 8);
            if (n == 0) yp[t + j] = fmaf(Dv, xs[j], p);
        }
    }
}

// ================= combine + transpose -> bf16 hi/lo [b][t][d] =================
__global__ void combine_t(const float* __restrict__ xz, const float* __restrict__ yf,
                          const float* __restrict__ yb,
                          __nv_bfloat16* __restrict__ chi, __nv_bfloat16* __restrict__ clo)
{
    __shared__ float s[32][33];
    int b = blockIdx.z;
    int t0 = blockIdx.x * 32, d0 = blockIdx.y * 32;
    int tid = threadIdx.x;
    int tl = tid & 31, dg = tid >> 5;
    #pragma unroll
    for (int i = 0; i < 4; i++) {
        int d = d0 + dg + i * 8;
        int t = t0 + tl;
        size_t bd = (size_t)b * D_INNER + d;
        float z  = xz[((size_t)b * E2 + D_INNER + d) * L_SEQ + t];
        float sz = z / (1.f + __expf(-z));
        float v  = 0.5f * sz * (yf[bd * L_SEQ + t] + yb[bd * L_SEQ + (L_SEQ - 1 - t)]);
        s[dg + i * 8][tl] = v;
    }
    __syncthreads();
    #pragma unroll
    for (int i = 0; i < 4; i++) {
        int t = t0 + dg + i * 8;
        int d = d0 + tl;
        float v = s[tl][dg + i * 8];
        __nv_bfloat16 h = __float2bfloat16(v);
        size_t o = ((size_t)b * L_SEQ + t) * D_INNER + d;
        chi[o] = h;
        clo[o] = __float2bfloat16(v - __bfloat162float(h));
    }
}

// ================= host launcher =================
extern "C" void kernel_launch(void* const* d_in, const int* in_sizes, int n_in,
                              void* d_out, int out_size)
{
    (void)in_sizes; (void)n_in; (void)out_size;
    const float* hidden   = (const float*)d_in[0];
    const float* W_in     = (const float*)d_in[1];
    const float* conv_w   = (const float*)d_in[2];
    const float* conv_b   = (const float*)d_in[3];
    const float* conv_w_b = (const float*)d_in[4];
    const float* conv_b_b = (const float*)d_in[5];
    const float* W_x      = (const float*)d_in[6];
    const float* W_x_b    = (const float*)d_in[7];
    const float* W_dt     = (const float*)d_in[8];
    const float* b_dt     = (const float*)d_in[9];
    const float* W_dt_b   = (const float*)d_in[10];
    const float* b_dt_b   = (const float*)d_in[11];
    const float* A_log    = (const float*)d_in[12];
    const float* A_b_log  = (const float*)d_in[13];
    const float* Dp       = (const float*)d_in[14];
    const float* Dp_b     = (const float*)d_in[15];
    const float* W_out    = (const float*)d_in[16];

    float *xz, *xcb, *xdp, *dtb, *bcb, *yb_, *Pp, *qp, *hinp;
    __nv_bfloat16 *winh, *winl, *hidh, *hidl, *wouth, *woutl, *chi, *clo, *xth, *xtl, *wxph, *wxpl;
    cudaGetSymbolAddress((void**)&xz,   g_xz);
    cudaGetSymbolAddress((void**)&xcb,  g_xc);
    cudaGetSymbolAddress((void**)&xdp,  g_xdp);
    cudaGetSymbolAddress((void**)&dtb,  g_dt);
    cudaGetSymbolAddress((void**)&bcb,  g_bc);
    cudaGetSymbolAddress((void**)&yb_,  g_y);
    cudaGetSymbolAddress((void**)&Pp,   g_P);
    cudaGetSymbolAddress((void**)&qp,   g_q);
    cudaGetSymbolAddress((void**)&hinp, g_hin);
    cudaGetSymbolAddress((void**)&winh, g_winh);  cudaGetSymbolAddress((void**)&winl, g_winl);
    cudaGetSymbolAddress((void**)&hidh, g_hidh);  cudaGetSymbolAddress((void**)&hidl, g_hidl);
    cudaGetSymbolAddress((void**)&wouth, g_wouth); cudaGetSymbolAddress((void**)&woutl, g_woutl);
    cudaGetSymbolAddress((void**)&chi,  g_chi);   cudaGetSymbolAddress((void**)&clo,  g_clo);
    cudaGetSymbolAddress((void**)&xth,  g_xth);   cudaGetSymbolAddress((void**)&xtl,  g_xtl);
    cudaGetSymbolAddress((void**)&wxph, g_wxph);  cudaGetSymbolAddress((void**)&wxpl, g_wxpl);

    const size_t S_XC = (size_t)B_SZ * D_INNER * L_SEQ;
    const size_t S_BC = (size_t)B_SZ * L_SEQ * 32;
    float* xc0 = xcb;  float* xc1 = xcb + S_XC;
    float* dt0 = dtb;  float* dt1 = dtb + S_XC;
    float* bc0 = bcb;  float* bc1 = bcb + S_BC;
    float* y0  = yb_;  float* y1  = yb_ + S_XC;

    const int SMEM128 = 4 * (2 * 128 * GM_PAD * 2 + 2 * 128 * GM_PAD * 2);
    const int SMEM64  = 4 * (2 * 128 * GM_PAD * 2 + 2 * 64  * GM_PAD * 2);
    cudaFuncSetAttribute(gemm_mma<128>, cudaFuncAttributeMaxDynamicSharedMemorySize, SMEM128);
    cudaFuncSetAttribute(gemm_mma<64>,  cudaFuncAttributeMaxDynamicSharedMemorySize, SMEM64);

    dim3 blk(256);

    // 0) merged prep: bf16 splits + padded W_x
    prep_kernel<<<dim3((B_SZ * L_SEQ * D_MODEL + 255) / 256, 4), blk>>>(
        W_in, hidden, W_out, W_x, W_x_b,
        winh, winl, hidh, hidl, wouth, woutl, wxph, wxpl);

    // 1) xz = W_in @ hidden^T
    gemm_mma<128><<<dim3(L_SEQ / 128, E2 / 128, B_SZ), blk, SMEM128>>>(
        winh, winl, hidh, hidl, xz, D_MODEL, L_SEQ,
        0L, 0L, (long)L_SEQ * D_MODEL, 0L, (long)E2 * L_SEQ, 0L);

    // 2) conv + silu
    conv_silu_t<<<dim3(L_SEQ / 32, D_INNER / 32, 4), blk>>>(
        xz, conv_w, conv_b, conv_w_b, conv_b_b, xc0, xc1, xth, xtl);

    // 3) x_dbl = W_x(padded) @ xc^T
    gemm_mma<64><<<dim3(L_SEQ / 64, 1, 4), blk, SMEM64>>>(
        wxph, wxpl, xth, xtl, xdp, D_INNER, L_SEQ,
        0L, (long)128 * D_INNER,
        (long)L_SEQ * D_INNER, (long)B_SZ * L_SEQ * D_INNER,
        (long)128 * L_SEQ, (long)B_SZ * 128 * L_SEQ);

    // 4) dt
    dt_kernel2<<<dim3(L_SEQ / 256, D_INNER / DT_DC, 4), blk>>>(
        xdp, W_dt, W_dt_b, b_dt, b_dt_b, dt0, dt1);

    // 5) B/C transpose
    bc_kernel<<<(2 * B_SZ * L_SEQ * 32) / 256, blk>>>(xdp, bc0, bc1);

    // 6) chunked selective scan
    scan_part1<<<dim3(R_TOT / 16, NCH), blk>>>(
        xc0, xc1, dt0, dt1, bc0, bc1, A_log, A_b_log, Pp, qp);
    scan_prefix<<<(R_TOT * D_STATE) / 256, blk>>>(Pp, qp, hinp);
    scan_part2<<<dim3(R_TOT / 16, NCH), blk>>>(
        xc0, xc1, dt0, dt1, bc0, bc1, A_log, A_b_log, Dp, Dp_b, hinp, y0, y1);

    // 7) combine -> transposed bf16 hi/lo
    combine_t<<<dim3(L_SEQ / 32, D_INNER / 32, B_SZ), blk>>>(xz, y0, y1, chi, clo);

    // 8) out = comb @ W_out^T
    gemm_mma<64><<<dim3(D_MODEL / 64, L_SEQ / 128, B_SZ), blk, SMEM64>>>(
        chi, clo, wouth, woutl, (float*)d_out, D_INNER, D_MODEL,
        (long)L_SEQ * D_INNER, 0L, 0L, 0L, (long)L_SEQ * D_MODEL, 0L);
}